// round 1
// baseline (speedup 1.0000x reference)
#include <cuda_runtime.h>

// Problem constants
#define BB 16
#define DD 256
#define TT 2048
#define KK 8192
#define NN (BB*TT)          // 32768 tokens
#define QN (BB*DD*TT)       // 8388608 quantized elements

// GEMM/argmin tiling
#define MT 128              // tokens per block
#define NT 128              // codes per tile
#define KC 16               // D-chunk
#define EPAD 132            // padded smem stride for emb tile (16B-aligned rows)

#define P2_BLOCKS (QN/1024) // 8192 gather/loss blocks

// Scratch (no allocations allowed -> device globals)
__device__ float g_norms[KK];
__device__ float g_zn2[NN];
__device__ int   g_idx[NN];
__device__ float g_partials[P2_BLOCKS];

// ---------------- kernel 0: codebook row norms (fp32, sequential-d FMA) ----------
__global__ void norms_kernel(const float* __restrict__ emb) {
    int k = blockIdx.x * blockDim.x + threadIdx.x;
    if (k >= KK) return;
    const float4* row = (const float4*)(emb + (size_t)k * DD);
    float s = 0.f;
#pragma unroll
    for (int i = 0; i < DD/4; i++) {
        float4 v = row[i];
        s = fmaf(v.x, v.x, s);
        s = fmaf(v.y, v.y, s);
        s = fmaf(v.z, v.z, s);
        s = fmaf(v.w, v.w, s);
    }
    g_norms[k] = s;
}

// ---------------- kernel 0b: per-token ||z||^2 ------------------------------------
__global__ void zn2_kernel(const float* __restrict__ z) {
    int n = blockIdx.x * blockDim.x + threadIdx.x;
    if (n >= NN) return;
    int b = n / TT, t = n % TT;
    const float* base = z + (size_t)b * DD * TT + t;
    float s = 0.f;
#pragma unroll 8
    for (int d = 0; d < DD; d++) {
        float v = base[(size_t)d * TT];
        s = fmaf(v, v, s);
    }
    g_zn2[n] = s;
}

// ---------------- kernel 1: fused distance GEMM + argmin --------------------------
// Block: 256 threads = 16x16 grid of (ty, tx); each thread owns 8 tokens x 8 codes.
// Tile: MT=128 tokens x NT=128 codes, D accumulated in KC=16 smem chunks.
__global__ __launch_bounds__(256) void
argmin_kernel(const float* __restrict__ z, const float* __restrict__ emb) {
    __shared__ __align__(16) float zs[KC][MT];
    __shared__ __align__(16) float es[KC][EPAD];
    __shared__ float rv[MT][16];
    __shared__ int   ri[MT][16];

    int tid = threadIdx.x;
    int tx = tid & 15, ty = tid >> 4;
    int token0 = blockIdx.x * MT;               // tile never straddles a batch (2048 % 128 == 0)
    int b = token0 / TT, t0 = token0 % TT;
    const float* zbase = z + (size_t)b * DD * TT + t0;

    float zn2v[8];
#pragma unroll
    for (int i = 0; i < 8; i++) zn2v[i] = g_zn2[token0 + ty*8 + i];

    float minv[8]; int mini[8];
#pragma unroll
    for (int i = 0; i < 8; i++) { minv[i] = 3.4028235e38f; mini[i] = 0; }

    for (int k0 = 0; k0 < KK; k0 += NT) {
        float acc[8][8];
#pragma unroll
        for (int i = 0; i < 8; i++)
#pragma unroll
            for (int j = 0; j < 8; j++) acc[i][j] = 0.f;

        for (int d0 = 0; d0 < DD; d0 += KC) {
            __syncthreads();
            // z chunk: [KC][MT], rows are contiguous-token slabs (coalesced float4)
            {
                int r = tid >> 5;        // 0..7
                int c = tid & 31;        // float4 column
#pragma unroll
                for (int h = 0; h < 2; h++) {
                    int rr = r + h*8;
                    float4 v = *(const float4*)(zbase + (size_t)(d0 + rr) * TT + c*4);
                    *(float4*)&zs[rr][c*4] = v;
                }
            }
            // emb chunk: transpose [code][d] -> es[d][code]
#pragma unroll
            for (int h = 0; h < 2; h++) {
                int f = tid + h*256;     // 0..511
                int code = f >> 2, d4 = (f & 3) * 4;
                float4 v = *(const float4*)(emb + (size_t)(k0 + code) * DD + d0 + d4);
                es[d4+0][code] = v.x;
                es[d4+1][code] = v.y;
                es[d4+2][code] = v.z;
                es[d4+3][code] = v.w;
            }
            __syncthreads();
#pragma unroll
            for (int d = 0; d < KC; d++) {
                float za[8], ea[8];
                *(float4*)&za[0] = *(const float4*)&zs[d][ty*8];
                *(float4*)&za[4] = *(const float4*)&zs[d][ty*8 + 4];
                *(float4*)&ea[0] = *(const float4*)&es[d][tx*8];
                *(float4*)&ea[4] = *(const float4*)&es[d][tx*8 + 4];
#pragma unroll
                for (int i = 0; i < 8; i++)
#pragma unroll
                    for (int j = 0; j < 8; j++)
                        acc[i][j] = fmaf(za[i], ea[j], acc[i][j]);
            }
        }

        // distances = fl( fl(zn2 + ek2) - 2*dot ), running argmin (lowest idx on ties)
        float cn[8];
#pragma unroll
        for (int j = 0; j < 8; j++) cn[j] = g_norms[k0 + tx*8 + j];
#pragma unroll
        for (int i = 0; i < 8; i++) {
#pragma unroll
            for (int j = 0; j < 8; j++) {
                float s = zn2v[i] + cn[j];
                float dist = s - 2.f * acc[i][j];   // 2*acc exact; single rounding on sub
                int idx = k0 + tx*8 + j;
                if (dist < minv[i] || (dist == minv[i] && idx < mini[i])) {
                    minv[i] = dist; mini[i] = idx;
                }
            }
        }
    }

    // cross-thread (tx) reduction per token
    __syncthreads();
#pragma unroll
    for (int i = 0; i < 8; i++) { rv[ty*8 + i][tx] = minv[i]; ri[ty*8 + i][tx] = mini[i]; }
    __syncthreads();
    if (tid < MT) {
        float bv = rv[tid][0]; int bi = ri[tid][0];
#pragma unroll
        for (int x = 1; x < 16; x++) {
            float v = rv[tid][x]; int id = ri[tid][x];
            if (v < bv || (v == bv && id < bi)) { bv = v; bi = id; }
        }
        g_idx[token0 + tid] = bi;
    }
}

// ---------------- kernel 2: gather quantized + partial loss -----------------------
// Each thread handles 4 consecutive t for one (b,d): coalesced z read + out write.
__global__ __launch_bounds__(256) void
gather_loss_kernel(const float* __restrict__ z, const float* __restrict__ emb,
                   float* __restrict__ out) {
    __shared__ float red[256];
    int unit = blockIdx.x * 256 + threadIdx.x;
    int e0 = unit * 4;                  // flat index into [B,D,T]
    int t  = e0 % TT;
    int bd = e0 / TT;
    int d  = bd % DD;
    int b  = bd / DD;
    int nb = b * TT + t;

    float4 zv = *(const float4*)(z + e0);
    int i0 = g_idx[nb + 0], i1 = g_idx[nb + 1], i2 = g_idx[nb + 2], i3 = g_idx[nb + 3];
    float4 qv;
    qv.x = emb[(size_t)i0 * DD + d];
    qv.y = emb[(size_t)i1 * DD + d];
    qv.z = emb[(size_t)i2 * DD + d];
    qv.w = emb[(size_t)i3 * DD + d];
    *(float4*)(out + e0) = qv;          // quantized_st == quantized numerically

    float dx = qv.x - zv.x, dy = qv.y - zv.y, dz = qv.z - zv.z, dw = qv.w - zv.w;
    red[threadIdx.x] = dx*dx + dy*dy + dz*dz + dw*dw;
    __syncthreads();
#pragma unroll
    for (int o = 128; o > 0; o >>= 1) {
        if (threadIdx.x < o) red[threadIdx.x] += red[threadIdx.x + o];
        __syncthreads();
    }
    if (threadIdx.x == 0) g_partials[blockIdx.x] = red[0];  // deterministic (no atomics)
}

// ---------------- kernel 3: finalize loss (fixed-order double reduce) -------------
__global__ void finalize_kernel(float* __restrict__ out, int out_size) {
    __shared__ double red[256];
    double s = 0.0;
    for (int i = threadIdx.x; i < P2_BLOCKS; i += 256) s += (double)g_partials[i];
    red[threadIdx.x] = s;
    __syncthreads();
#pragma unroll
    for (int o = 128; o > 0; o >>= 1) {
        if (threadIdx.x < o) red[threadIdx.x] += red[threadIdx.x + o];
        __syncthreads();
    }
    if (threadIdx.x == 0 && out_size > QN) {
        // loss = q_latent + 0.25*e_latent; both equal mean((q-z)^2) numerically
        out[QN] = (float)(1.25 * red[0] / (double)QN);
    }
}

// ---------------- kernel 4: indices as output dtype -------------------------------
__global__ void idxout_kernel(float* __restrict__ out) {
    int n = blockIdx.x * 256 + threadIdx.x;
    if (n < NN) out[QN + 1 + n] = (float)g_idx[n];
}

extern "C" void kernel_launch(void* const* d_in, const int* in_sizes, int n_in,
                              void* d_out, int out_size) {
    const float* z   = (const float*)d_in[0];
    const float* emb = (const float*)d_in[1];
    float* out = (float*)d_out;

    norms_kernel<<<KK/256, 256>>>(emb);
    zn2_kernel<<<NN/256, 256>>>(z);
    argmin_kernel<<<NN/MT, 256>>>(z, emb);
    gather_loss_kernel<<<QN/1024, 256>>>(z, emb, out);
    finalize_kernel<<<1, 256>>>(out, out_size);
    if (out_size >= QN + 1 + NN)
        idxout_kernel<<<(NN + 255)/256, 256>>>(out);
}